// round 3
// baseline (speedup 1.0000x reference)
#include <cuda_runtime.h>
#include <cuda_bf16.h>
#include <math.h>

// Problem constants (fixed shapes per reference)
#define NN 50000
#define EE 800000
#define GG 64
#define FIN 64
#define HH 64
#define RR 3
#define CC 10
#define YW 832   // packed output width: 128(fs) + 64(skip) + 192(xr) + 384(fm) + 64(xp)

// Column layout in Y / Wcat:
//  [0,128)   fs   = x @ skip_film_W + skip_film_b
//  [128,192) skip = x @ skip_W
//  [192,384) xr   : r*64 + h  = x @ film_lin_W[r]
//  [384,768) fm   : r*128 + c = x @ film_film_W[r] + film_film_b[r]   (beta=c<64, gamma=c>=64)
//  [768,832) xp   = x @ gat_W

// ---------------- scratch (device globals; no allocation allowed) -------------
__device__ float    d_Y[(size_t)NN * YW];
__device__ float    d_Wcat[64 * YW];
__device__ float    d_bcat[YW];
__device__ float    d_feats[(size_t)NN * 128];
__device__ float    d_as[NN];
__device__ float    d_ad[NN];
__device__ unsigned d_menc[NN];
__device__ float    d_denomg[NN];
__device__ int      d_cnt[NN * RR];
__device__ int      d_poolmax[GG * 128];   // float bits, values >= 0
__device__ float    d_poolsum[GG * 128];
__device__ int      d_gcnt[GG];

// ---------------- helpers ----------------
__device__ __forceinline__ float lrelu(float x) { return x > 0.f ? x : 0.2f * x; }
__device__ __forceinline__ float frelu(float x) { return fmaxf(x, 0.f); }
// order-preserving encode for float atomicMax over full range
__device__ __forceinline__ unsigned fenc(float f) {
    unsigned u = __float_as_uint(f);
    return (u & 0x80000000u) ? ~u : (u | 0x80000000u);
}
__device__ __forceinline__ float fdec(unsigned u) {
    return (u & 0x80000000u) ? __uint_as_float(u & 0x7fffffffu) : __uint_as_float(~u);
}

// ---------------- 1. pack weights + biases ----------------
__global__ void pack_kernel(const float* __restrict__ skip_film_W,
                            const float* __restrict__ skip_W,
                            const float* __restrict__ film_lin_W,
                            const float* __restrict__ film_film_W,
                            const float* __restrict__ film_film_b,
                            const float* __restrict__ skip_film_b,
                            const float* __restrict__ gat_W) {
    int stride = blockDim.x * gridDim.x;
    for (int idx = blockIdx.x * blockDim.x + threadIdx.x; idx < 64 * YW; idx += stride) {
        int d = idx / YW, j = idx % YW;
        float v;
        if (j < 128)        v = skip_film_W[d * 128 + j];
        else if (j < 192)   v = skip_W[d * 64 + (j - 128)];
        else if (j < 384) { int r = (j - 192) >> 6, h = (j - 192) & 63;
                            v = film_lin_W[r * 4096 + d * 64 + h]; }
        else if (j < 768) { int r = (j - 384) >> 7, c = (j - 384) & 127;
                            v = film_film_W[r * 8192 + d * 128 + c]; }
        else                v = gat_W[d * 64 + (j - 768)];
        d_Wcat[idx] = v;
    }
    for (int j = blockIdx.x * blockDim.x + threadIdx.x; j < YW; j += stride) {
        float b = 0.f;
        if (j < 128)                 b = skip_film_b[j];
        else if (j >= 384 && j < 768) { int r = (j - 384) >> 7, c = (j - 384) & 127;
                                        b = film_film_b[r * 128 + c]; }
        d_bcat[j] = b;
    }
}

// ---------------- 2. zero scratch ----------------
__global__ void zero_kernel() {
    int stride = blockDim.x * gridDim.x;
    int t = blockIdx.x * blockDim.x + threadIdx.x;
    for (int i = t; i < NN * RR; i += stride) d_cnt[i] = 0;
    for (int i = t; i < NN; i += stride)      d_denomg[i] = 0.f;
    for (int i = t; i < GG * 128; i += stride) { d_poolmax[i] = 0; d_poolsum[i] = 0.f; }
    for (int i = t; i < GG; i += stride)      d_gcnt[i] = 0;
}

// ---------------- 3. fused GEMM: Y = x @ Wcat + bcat ----------------
__global__ __launch_bounds__(256) void gemm_kernel(const float* __restrict__ A, int n) {
    __shared__ float As[64][68];   // As[k][row] (transposed)
    __shared__ float Bs[64][68];   // Bs[k][col]
    int row0 = blockIdx.x * 64;
    int col0 = blockIdx.y * 64;
    int tid = threadIdx.x;

    // load A tile (64 rows x 64 k), transpose into As
    #pragma unroll
    for (int i = 0; i < 4; i++) {
        int e = i * 256 + tid;          // 0..1023 float4 slots
        int r = e >> 4;
        int k4 = (e & 15) << 2;
        float4 v = make_float4(0.f, 0.f, 0.f, 0.f);
        if (row0 + r < n) v = *(const float4*)(A + (size_t)(row0 + r) * 64 + k4);
        As[k4 + 0][r] = v.x; As[k4 + 1][r] = v.y; As[k4 + 2][r] = v.z; As[k4 + 3][r] = v.w;
    }
    // load B tile
    #pragma unroll
    for (int i = 0; i < 4; i++) {
        int e = i * 256 + tid;
        int k = e >> 4;
        int c4 = (e & 15) << 2;
        *(float4*)&Bs[k][c4] = *(const float4*)(d_Wcat + k * YW + col0 + c4);
    }
    __syncthreads();

    int tx = tid & 15, ty = tid >> 4;
    float acc[4][4] = {};
    #pragma unroll
    for (int k = 0; k < 64; k++) {
        float4 a = *(const float4*)&As[k][ty << 2];
        float4 b = *(const float4*)&Bs[k][tx << 2];
        float av[4] = {a.x, a.y, a.z, a.w};
        float bv[4] = {b.x, b.y, b.z, b.w};
        #pragma unroll
        for (int i = 0; i < 4; i++)
            #pragma unroll
            for (int j = 0; j < 4; j++)
                acc[i][j] = fmaf(av[i], bv[j], acc[i][j]);
    }

    int c = col0 + (tx << 2);
    float4 bias = *(const float4*)&d_bcat[c];
    #pragma unroll
    for (int i = 0; i < 4; i++) {
        int r = row0 + (ty << 2) + i;
        if (r < n) {
            float4 o = make_float4(acc[i][0] + bias.x, acc[i][1] + bias.y,
                                   acc[i][2] + bias.z, acc[i][3] + bias.w);
            *(float4*)(d_Y + (size_t)r * YW + c) = o;
        }
    }
}

// ---------------- 4. node epilogue: skip path, alpha dots, m init ----------------
__global__ void node_epi_kernel(int n, const float* __restrict__ att_src,
                                const float* __restrict__ att_dst) {
    int w = (blockIdx.x * blockDim.x + threadIdx.x) >> 5;
    int l = threadIdx.x & 31;
    if (w >= n) return;
    const float* yr = d_Y + (size_t)w * YW;
    float* fr = d_feats + (size_t)w * 128;
    #pragma unroll
    for (int p = 0; p < 2; p++) {
        int h = l + p * 32;
        float f0 = yr[h], mul = yr[64 + h], sk = yr[128 + h];
        fr[h] = frelu(mul * sk + f0);    // FiLM skip path (pre-agg)
        fr[64 + h] = 0.f;                // GAT accumulator
    }
    float xp0 = yr[768 + l], xp1 = yr[768 + 32 + l];
    float ps = xp0 * att_src[l] + xp1 * att_src[l + 32];
    float pd = xp0 * att_dst[l] + xp1 * att_dst[l + 32];
    #pragma unroll
    for (int off = 16; off > 0; off >>= 1) {
        ps += __shfl_down_sync(0xffffffffu, ps, off);
        pd += __shfl_down_sync(0xffffffffu, pd, off);
    }
    if (l == 0) {
        d_as[w] = ps;
        d_ad[w] = pd;
        d_menc[w] = fenc(lrelu(ps + pd));   // self-loop seeds the max
    }
}

// ---------------- 5. edge pass 1: counts + GAT max ----------------
__global__ void edge_p1_kernel(int ne, const int* __restrict__ ei,
                               const int* __restrict__ et) {
    int e = blockIdx.x * blockDim.x + threadIdx.x;
    if (e >= ne) return;
    int s = ei[e], d = ei[ne + e], t = et[e];
    atomicAdd(&d_cnt[d * RR + t], 1);
    float v = lrelu(d_as[s] + d_ad[d]);
    atomicMax(&d_menc[d], fenc(v));
}

// ---------------- 6. GAT softmax denominator (edges + self loops) ----------------
__global__ void denom_kernel(int n, int ne, const int* __restrict__ ei) {
    int i = blockIdx.x * blockDim.x + threadIdx.x;
    if (i < n) {
        float e = lrelu(d_as[i] + d_ad[i]);
        atomicAdd(&d_denomg[i], expf(e - fdec(d_menc[i])));
    } else if (i < n + ne) {
        int e = i - n;
        int s = ei[e], d = ei[ne + e];
        float v = lrelu(d_as[s] + d_ad[d]);
        atomicAdd(&d_denomg[d], expf(v - fdec(d_menc[d])));
    }
}

// ---------------- 7. fused vector pass: FiLM messages + GAT gather ----------------
__global__ void edge_p3_kernel(int n, int ne, const int* __restrict__ ei,
                               const int* __restrict__ et) {
    int w = (blockIdx.x * blockDim.x + threadIdx.x) >> 5;
    int l = threadIdx.x & 31;
    if (w < ne) {
        int s = ei[w], d = ei[ne + w], t = et[w];
        float dn = fmaxf((float)d_cnt[d * RR + t], 1.f);
        float wgt = expf(lrelu(d_as[s] + d_ad[d]) - fdec(d_menc[d])) / d_denomg[d];
        const float* gB = d_Y + (size_t)d * YW + 384 + t * 128;  // beta at [h], gamma at [64+h]
        const float* xr = d_Y + (size_t)s * YW + 192 + t * 64;
        const float* xp = d_Y + (size_t)s * YW + 768;
        float* fd = d_feats + (size_t)d * 128;
        #pragma unroll
        for (int p = 0; p < 2; p++) {
            int h = l + p * 32;
            float msg = frelu(gB[64 + h] * xr[h] + gB[h]) / dn;
            atomicAdd(&fd[h], msg);
            atomicAdd(&fd[64 + h], wgt * xp[h]);
        }
    } else if (w < ne + n) {
        int v = w - ne;   // GAT self loop
        float wgt = expf(lrelu(d_as[v] + d_ad[v]) - fdec(d_menc[v])) / d_denomg[v];
        const float* xp = d_Y + (size_t)v * YW + 768;
        float* fd = d_feats + (size_t)v * 128;
        #pragma unroll
        for (int p = 0; p < 2; p++) {
            int h = l + p * 32;
            atomicAdd(&fd[64 + h], wgt * xp[h]);
        }
    }
}

// ---------------- 8. per-graph pooling ----------------
__global__ void pool_kernel(int n, const int* __restrict__ gb,
                            const float* __restrict__ gat_b) {
    int w = (blockIdx.x * blockDim.x + threadIdx.x) >> 5;
    int l = threadIdx.x & 31;
    if (w >= n) return;
    int g = gb[w];
    const float* fr = d_feats + (size_t)w * 128;
    #pragma unroll
    for (int p = 0; p < 4; p++) {
        int j = l + p * 32;
        float v = fr[j];
        v = (j < 64) ? frelu(v) : frelu(v + gat_b[j - 64]);
        atomicMax(&d_poolmax[g * 128 + j], __float_as_int(v));  // v >= 0
        atomicAdd(&d_poolsum[g * 128 + j], v);
    }
    if (l == 0) atomicAdd(&d_gcnt[g], 1);
}

// ---------------- 9. final MLP + log_softmax ----------------
__global__ void final_kernel(const float* __restrict__ lin_W, const float* __restrict__ lin_b,
                             const float* __restrict__ fc_W, const float* __restrict__ fc_b,
                             float* __restrict__ out) {
    int g = blockIdx.x, t = threadIdx.x;   // 64 threads
    __shared__ float pooled[256];
    __shared__ float hid[64];
    __shared__ float logits[CC];
    __shared__ float mx, lse;
    float cm = fmaxf((float)d_gcnt[g], 1.f);
    for (int j = t; j < 128; j += 64) {
        pooled[j] = __int_as_float(d_poolmax[g * 128 + j]);
        pooled[128 + j] = d_poolsum[g * 128 + j] / cm;
    }
    __syncthreads();
    float hs = lin_b[t];
    #pragma unroll 4
    for (int k = 0; k < 256; k++) hs = fmaf(pooled[k], lin_W[k * 64 + t], hs);
    hid[t] = frelu(hs);
    __syncthreads();
    if (t < CC) {
        float s = fc_b[t];
        #pragma unroll
        for (int h = 0; h < 64; h++) s = fmaf(hid[h], fc_W[h * CC + t], s);
        logits[t] = s;
    }
    __syncthreads();
    if (t == 0) {
        float m = logits[0];
        #pragma unroll
        for (int c = 1; c < CC; c++) m = fmaxf(m, logits[c]);
        float sum = 0.f;
        #pragma unroll
        for (int c = 0; c < CC; c++) sum += expf(logits[c] - m);
        mx = m; lse = logf(sum);
    }
    __syncthreads();
    if (t < CC) out[g * CC + t] = logits[t] - mx - lse;
}

// ---------------- launch ----------------
extern "C" void kernel_launch(void* const* d_in, const int* in_sizes, int n_in,
                              void* d_out, int out_size) {
    const float* x           = (const float*)d_in[0];
    const int*   edge_index  = (const int*)d_in[1];
    const int*   edge_type   = (const int*)d_in[2];
    const int*   graph_batch = (const int*)d_in[3];
    const float* film_lin_W  = (const float*)d_in[4];
    const float* film_film_W = (const float*)d_in[5];
    const float* film_film_b = (const float*)d_in[6];
    const float* skip_W      = (const float*)d_in[7];
    const float* skip_film_W = (const float*)d_in[8];
    const float* skip_film_b = (const float*)d_in[9];
    const float* gat_W       = (const float*)d_in[10];
    const float* gat_att_src = (const float*)d_in[11];
    const float* gat_att_dst = (const float*)d_in[12];
    const float* gat_b       = (const float*)d_in[13];
    const float* lin_W       = (const float*)d_in[14];
    const float* lin_b       = (const float*)d_in[15];
    const float* fc_W        = (const float*)d_in[16];
    const float* fc_b        = (const float*)d_in[17];
    float* out = (float*)d_out;

    int n = in_sizes[0] / FIN;     // 50000
    int ne = in_sizes[2];          // 800000

    pack_kernel<<<64, 256>>>(skip_film_W, skip_W, film_lin_W, film_film_W,
                             film_film_b, skip_film_b, gat_W);
    zero_kernel<<<256, 256>>>();
    dim3 ggrid((n + 63) / 64, YW / 64);
    gemm_kernel<<<ggrid, 256>>>(x, n);
    node_epi_kernel<<<(n + 7) / 8, 256>>>(n, gat_att_src, gat_att_dst);
    edge_p1_kernel<<<(ne + 255) / 256, 256>>>(ne, edge_index, edge_type);
    denom_kernel<<<(n + ne + 255) / 256, 256>>>(n, ne, edge_index);
    edge_p3_kernel<<<(ne + n + 7) / 8, 256>>>(n, ne, edge_index, edge_type);
    pool_kernel<<<(n + 7) / 8, 256>>>(n, graph_batch, gat_b);
    final_kernel<<<GG, 64>>>(lin_W, lin_b, fc_W, fc_b, out);
}

// round 4
// speedup vs baseline: 1.2663x; 1.2663x over previous
#include <cuda_runtime.h>
#include <cuda_bf16.h>
#include <math.h>

// Problem constants (fixed shapes per reference)
#define NN 50000
#define EE 800000
#define GG 64
#define FIN 64
#define HH 64
#define RR 3
#define CC 10
#define YW 832   // packed output width: 128(fs) + 64(skip) + 192(xr) + 384(fm) + 64(xp)

// Column layout in Y / Wcat:
//  [0,128)   fs   = x @ skip_film_W + skip_film_b
//  [128,192) skip = x @ skip_W
//  [192,384) xr   : r*64 + h  = x @ film_lin_W[r]
//  [384,768) fm   : r*128 + c = x @ film_film_W[r] + film_film_b[r]   (beta=c<64, gamma=c>=64)
//  [768,832) xp   = x @ gat_W

// ---------------- scratch (device globals; no allocation allowed) -------------
__device__ float    d_Y[(size_t)NN * YW];
__device__ float    d_Wcat[64 * YW];
__device__ float    d_bcat[YW];
__device__ float    d_feats[(size_t)NN * 128];
__device__ float    d_as[NN];
__device__ float    d_ad[NN];
__device__ unsigned d_menc[NN];
__device__ float    d_denomg[NN];
__device__ int      d_cnt[NN * RR];
__device__ int      d_poolmax[GG * 128];   // float bits, values >= 0
__device__ float    d_poolsum[GG * 128];
__device__ int      d_gcnt[GG];

// ---------------- helpers ----------------
__device__ __forceinline__ float lrelu(float x) { return x > 0.f ? x : 0.2f * x; }
__device__ __forceinline__ float frelu(float x) { return fmaxf(x, 0.f); }
// order-preserving encode for float atomicMax over full range
__device__ __forceinline__ unsigned fenc(float f) {
    unsigned u = __float_as_uint(f);
    return (u & 0x80000000u) ? ~u : (u | 0x80000000u);
}
__device__ __forceinline__ float fdec(unsigned u) {
    return (u & 0x80000000u) ? __uint_as_float(u & 0x7fffffffu) : __uint_as_float(~u);
}
__device__ __forceinline__ unsigned f2tf(float f) {
    unsigned u;
    asm("cvt.rna.tf32.f32 %0, %1;" : "=r"(u) : "f"(f));
    return u;
}
__device__ __forceinline__ void mma_tf32(float* d, const unsigned* a, const unsigned* b) {
    asm volatile(
        "mma.sync.aligned.m16n8k8.row.col.f32.tf32.tf32.f32 "
        "{%0,%1,%2,%3}, {%4,%5,%6,%7}, {%8,%9}, {%0,%1,%2,%3};"
        : "+f"(d[0]), "+f"(d[1]), "+f"(d[2]), "+f"(d[3])
        : "r"(a[0]), "r"(a[1]), "r"(a[2]), "r"(a[3]), "r"(b[0]), "r"(b[1]));
}
__device__ __forceinline__ void red_add_v4(float* p, float a, float b, float c, float d) {
    asm volatile("red.global.add.v4.f32 [%0], {%1,%2,%3,%4};"
                 :: "l"(p), "f"(a), "f"(b), "f"(c), "f"(d) : "memory");
}

// ---------------- 1. pack weights + biases ----------------
__global__ void pack_kernel(const float* __restrict__ skip_film_W,
                            const float* __restrict__ skip_W,
                            const float* __restrict__ film_lin_W,
                            const float* __restrict__ film_film_W,
                            const float* __restrict__ film_film_b,
                            const float* __restrict__ skip_film_b,
                            const float* __restrict__ gat_W) {
    int stride = blockDim.x * gridDim.x;
    for (int idx = blockIdx.x * blockDim.x + threadIdx.x; idx < 64 * YW; idx += stride) {
        int d = idx / YW, j = idx % YW;
        float v;
        if (j < 128)        v = skip_film_W[d * 128 + j];
        else if (j < 192)   v = skip_W[d * 64 + (j - 128)];
        else if (j < 384) { int r = (j - 192) >> 6, h = (j - 192) & 63;
                            v = film_lin_W[r * 4096 + d * 64 + h]; }
        else if (j < 768) { int r = (j - 384) >> 7, c = (j - 384) & 127;
                            v = film_film_W[r * 8192 + d * 128 + c]; }
        else                v = gat_W[d * 64 + (j - 768)];
        d_Wcat[idx] = v;
    }
    for (int j = blockIdx.x * blockDim.x + threadIdx.x; j < YW; j += stride) {
        float b = 0.f;
        if (j < 128)                 b = skip_film_b[j];
        else if (j >= 384 && j < 768) { int r = (j - 384) >> 7, c = (j - 384) & 127;
                                        b = film_film_b[r * 128 + c]; }
        d_bcat[j] = b;
    }
}

// ---------------- 2. zero scratch ----------------
__global__ void zero_kernel() {
    int stride = blockDim.x * gridDim.x;
    int t = blockIdx.x * blockDim.x + threadIdx.x;
    for (int i = t; i < NN * RR; i += stride) d_cnt[i] = 0;
    for (int i = t; i < NN; i += stride)      d_denomg[i] = 0.f;
    for (int i = t; i < GG * 128; i += stride) { d_poolmax[i] = 0; d_poolsum[i] = 0.f; }
    for (int i = t; i < GG; i += stride)      d_gcnt[i] = 0;
}

// ---------------- 3. tensor-core GEMM (3xTF32 split): Y = x @ Wcat + bcat ------
// Block tile: M=128, N=64, K=64 (full). 256 threads = 8 warps (4 m-warps x 2 n-warps),
// each warp computes a 32x32 tile = 2 (m16) x 4 (n8) mma fragments.
__global__ __launch_bounds__(256) void gemm_tc_kernel(const float* __restrict__ A, int n) {
    __shared__ float As[128][68];   // [m][k], stride 68 -> conflict-free frag loads
    __shared__ float Bs[64][72];    // [k][n], stride 72 -> conflict-free frag loads
    int row0 = blockIdx.x * 128;
    int col0 = blockIdx.y * 64;
    int tid = threadIdx.x;

    // load A tile: 128 rows x 64 k  (2048 float4, 8 per thread)
    #pragma unroll
    for (int i = 0; i < 8; i++) {
        int e = i * 256 + tid;
        int r = e >> 4;
        int c4 = (e & 15) << 2;
        float4 v = make_float4(0.f, 0.f, 0.f, 0.f);
        if (row0 + r < n) v = *(const float4*)(A + (size_t)(row0 + r) * 64 + c4);
        As[r][c4] = v.x; As[r][c4 + 1] = v.y; As[r][c4 + 2] = v.z; As[r][c4 + 3] = v.w;
    }
    // load B tile: 64 k x 64 n
    #pragma unroll
    for (int i = 0; i < 4; i++) {
        int e = i * 256 + tid;
        int k = e >> 4;
        int c4 = (e & 15) << 2;
        float4 v = *(const float4*)(d_Wcat + k * YW + col0 + c4);
        Bs[k][c4] = v.x; Bs[k][c4 + 1] = v.y; Bs[k][c4 + 2] = v.z; Bs[k][c4 + 3] = v.w;
    }
    __syncthreads();

    int warp = tid >> 5, lane = tid & 31;
    int wm = (warp >> 1) * 32;   // m offset of warp tile
    int wn = (warp & 1) * 32;    // n offset of warp tile
    int lr = lane >> 2;          // 0..7
    int lc = lane & 3;           // 0..3

    float acc[2][4][4] = {};
    #pragma unroll
    for (int k0 = 0; k0 < 64; k0 += 8) {
        unsigned abig[2][4], asml[2][4];
        #pragma unroll
        for (int mi = 0; mi < 2; mi++) {
            int r = wm + mi * 16 + lr;
            float a0 = As[r][k0 + lc];
            float a1 = As[r + 8][k0 + lc];
            float a2 = As[r][k0 + 4 + lc];
            float a3 = As[r + 8][k0 + 4 + lc];
            abig[mi][0] = f2tf(a0); asml[mi][0] = f2tf(a0 - __uint_as_float(abig[mi][0]));
            abig[mi][1] = f2tf(a1); asml[mi][1] = f2tf(a1 - __uint_as_float(abig[mi][1]));
            abig[mi][2] = f2tf(a2); asml[mi][2] = f2tf(a2 - __uint_as_float(abig[mi][2]));
            abig[mi][3] = f2tf(a3); asml[mi][3] = f2tf(a3 - __uint_as_float(abig[mi][3]));
        }
        unsigned bbig[4][2], bsml[4][2];
        #pragma unroll
        for (int ni = 0; ni < 4; ni++) {
            int c = wn + ni * 8 + lr;
            float b0 = Bs[k0 + lc][c];
            float b1 = Bs[k0 + 4 + lc][c];
            bbig[ni][0] = f2tf(b0); bsml[ni][0] = f2tf(b0 - __uint_as_float(bbig[ni][0]));
            bbig[ni][1] = f2tf(b1); bsml[ni][1] = f2tf(b1 - __uint_as_float(bbig[ni][1]));
        }
        #pragma unroll
        for (int mi = 0; mi < 2; mi++)
            #pragma unroll
            for (int ni = 0; ni < 4; ni++) {
                mma_tf32(acc[mi][ni], abig[mi], bbig[ni]);   // big*big
                mma_tf32(acc[mi][ni], abig[mi], bsml[ni]);   // big*small
                mma_tf32(acc[mi][ni], asml[mi], bbig[ni]);   // small*big
            }
    }

    // epilogue: add bias, store float2 pairs (32B-sector aligned segments)
    #pragma unroll
    for (int mi = 0; mi < 2; mi++) {
        #pragma unroll
        for (int ni = 0; ni < 4; ni++) {
            int c = col0 + wn + ni * 8 + 2 * lc;
            float b0 = d_bcat[c], b1 = d_bcat[c + 1];
            int r0 = row0 + wm + mi * 16 + lr;
            if (r0 < n) {
                float2 o = make_float2(acc[mi][ni][0] + b0, acc[mi][ni][1] + b1);
                *(float2*)(d_Y + (size_t)r0 * YW + c) = o;
            }
            if (r0 + 8 < n) {
                float2 o = make_float2(acc[mi][ni][2] + b0, acc[mi][ni][3] + b1);
                *(float2*)(d_Y + (size_t)(r0 + 8) * YW + c) = o;
            }
        }
    }
}

// ---------------- 4. node epilogue: skip path, alpha dots, m init ----------------
__global__ void node_epi_kernel(int n, const float* __restrict__ att_src,
                                const float* __restrict__ att_dst) {
    int w = (blockIdx.x * blockDim.x + threadIdx.x) >> 5;
    int l = threadIdx.x & 31;
    if (w >= n) return;
    const float* yr = d_Y + (size_t)w * YW;
    float* fr = d_feats + (size_t)w * 128;
    #pragma unroll
    for (int p = 0; p < 2; p++) {
        int h = l + p * 32;
        float f0 = yr[h], mul = yr[64 + h], sk = yr[128 + h];
        fr[h] = frelu(mul * sk + f0);    // FiLM skip path (pre-agg)
        fr[64 + h] = 0.f;                // GAT accumulator
    }
    float xp0 = yr[768 + l], xp1 = yr[768 + 32 + l];
    float ps = xp0 * att_src[l] + xp1 * att_src[l + 32];
    float pd = xp0 * att_dst[l] + xp1 * att_dst[l + 32];
    #pragma unroll
    for (int off = 16; off > 0; off >>= 1) {
        ps += __shfl_down_sync(0xffffffffu, ps, off);
        pd += __shfl_down_sync(0xffffffffu, pd, off);
    }
    if (l == 0) {
        d_as[w] = ps;
        d_ad[w] = pd;
        d_menc[w] = fenc(lrelu(ps + pd));   // self-loop seeds the max
    }
}

// ---------------- 5. edge pass 1: counts + GAT max ----------------
__global__ void edge_p1_kernel(int ne, const int* __restrict__ ei,
                               const int* __restrict__ et) {
    int e = blockIdx.x * blockDim.x + threadIdx.x;
    if (e >= ne) return;
    int s = ei[e], d = ei[ne + e], t = et[e];
    atomicAdd(&d_cnt[d * RR + t], 1);
    float v = lrelu(d_as[s] + d_ad[d]);
    atomicMax(&d_menc[d], fenc(v));
}

// ---------------- 6. GAT softmax denominator (edges + self loops) ----------------
__global__ void denom_kernel(int n, int ne, const int* __restrict__ ei) {
    int i = blockIdx.x * blockDim.x + threadIdx.x;
    if (i < n) {
        float e = lrelu(d_as[i] + d_ad[i]);
        atomicAdd(&d_denomg[i], expf(e - fdec(d_menc[i])));
    } else if (i < n + ne) {
        int e = i - n;
        int s = ei[e], d = ei[ne + e];
        float v = lrelu(d_as[s] + d_ad[d]);
        atomicAdd(&d_denomg[d], expf(v - fdec(d_menc[d])));
    }
}

// ---------------- 7. fused vector pass: FiLM messages + GAT gather ----------------
// warp per edge; lanes 0-15: FiLM message (4 h each, one red.v4); lanes 16-31: GAT.
__global__ void edge_p3_kernel(int n, int ne, const int* __restrict__ ei,
                               const int* __restrict__ et) {
    int w = (blockIdx.x * blockDim.x + threadIdx.x) >> 5;
    int l = threadIdx.x & 31;
    if (w < ne) {
        int s = ei[w], d = ei[ne + w], t = et[w];
        float* fd = d_feats + (size_t)d * 128;
        if (l < 16) {
            int h = l << 2;
            float dn = fmaxf((float)d_cnt[d * RR + t], 1.f);
            float rdn = 1.f / dn;
            const float* gB = d_Y + (size_t)d * YW + 384 + t * 128;
            const float* xr = d_Y + (size_t)s * YW + 192 + t * 64;
            float4 beta = *(const float4*)(gB + h);
            float4 gamm = *(const float4*)(gB + 64 + h);
            float4 xv   = *(const float4*)(xr + h);
            red_add_v4(fd + h,
                       frelu(gamm.x * xv.x + beta.x) * rdn,
                       frelu(gamm.y * xv.y + beta.y) * rdn,
                       frelu(gamm.z * xv.z + beta.z) * rdn,
                       frelu(gamm.w * xv.w + beta.w) * rdn);
        } else {
            int h = (l - 16) << 2;
            float wgt = expf(lrelu(d_as[s] + d_ad[d]) - fdec(d_menc[d])) / d_denomg[d];
            const float* xp = d_Y + (size_t)s * YW + 768;
            float4 xv = *(const float4*)(xp + h);
            red_add_v4(fd + 64 + h, wgt * xv.x, wgt * xv.y, wgt * xv.z, wgt * xv.w);
        }
    } else if (w < ne + n) {
        int v = w - ne;   // GAT self loop
        if (l >= 16) {
            int h = (l - 16) << 2;
            float wgt = expf(lrelu(d_as[v] + d_ad[v]) - fdec(d_menc[v])) / d_denomg[v];
            const float* xp = d_Y + (size_t)v * YW + 768;
            float4 xv = *(const float4*)(xp + h);
            red_add_v4(d_feats + (size_t)v * 128 + 64 + h,
                       wgt * xv.x, wgt * xv.y, wgt * xv.z, wgt * xv.w);
        }
    }
}

// ---------------- 8. per-graph pooling ----------------
__global__ void pool_kernel(int n, const int* __restrict__ gb,
                            const float* __restrict__ gat_b) {
    int w = (blockIdx.x * blockDim.x + threadIdx.x) >> 5;
    int l = threadIdx.x & 31;
    if (w >= n) return;
    int g = gb[w];
    const float* fr = d_feats + (size_t)w * 128;
    #pragma unroll
    for (int p = 0; p < 4; p++) {
        int j = l + p * 32;
        float v = fr[j];
        v = (j < 64) ? frelu(v) : frelu(v + gat_b[j - 64]);
        atomicMax(&d_poolmax[g * 128 + j], __float_as_int(v));  // v >= 0
        atomicAdd(&d_poolsum[g * 128 + j], v);
    }
    if (l == 0) atomicAdd(&d_gcnt[g], 1);
}

// ---------------- 9. final MLP + log_softmax ----------------
__global__ void final_kernel(const float* __restrict__ lin_W, const float* __restrict__ lin_b,
                             const float* __restrict__ fc_W, const float* __restrict__ fc_b,
                             float* __restrict__ out) {
    int g = blockIdx.x, t = threadIdx.x;   // 64 threads
    __shared__ float pooled[256];
    __shared__ float hid[64];
    __shared__ float logits[CC];
    __shared__ float mx, lse;
    float cm = fmaxf((float)d_gcnt[g], 1.f);
    for (int j = t; j < 128; j += 64) {
        pooled[j] = __int_as_float(d_poolmax[g * 128 + j]);
        pooled[128 + j] = d_poolsum[g * 128 + j] / cm;
    }
    __syncthreads();
    float hs = lin_b[t];
    #pragma unroll 4
    for (int k = 0; k < 256; k++) hs = fmaf(pooled[k], lin_W[k * 64 + t], hs);
    hid[t] = frelu(hs);
    __syncthreads();
    if (t < CC) {
        float s = fc_b[t];
        #pragma unroll
        for (int h = 0; h < 64; h++) s = fmaf(hid[h], fc_W[h * CC + t], s);
        logits[t] = s;
    }
    __syncthreads();
    if (t == 0) {
        float m = logits[0];
        #pragma unroll
        for (int c = 1; c < CC; c++) m = fmaxf(m, logits[c]);
        float sum = 0.f;
        #pragma unroll
        for (int c = 0; c < CC; c++) sum += expf(logits[c] - m);
        mx = m; lse = logf(sum);
    }
    __syncthreads();
    if (t < CC) out[g * CC + t] = logits[t] - mx - lse;
}

// ---------------- launch ----------------
extern "C" void kernel_launch(void* const* d_in, const int* in_sizes, int n_in,
                              void* d_out, int out_size) {
    const float* x           = (const float*)d_in[0];
    const int*   edge_index  = (const int*)d_in[1];
    const int*   edge_type   = (const int*)d_in[2];
    const int*   graph_batch = (const int*)d_in[3];
    const float* film_lin_W  = (const float*)d_in[4];
    const float* film_film_W = (const float*)d_in[5];
    const float* film_film_b = (const float*)d_in[6];
    const float* skip_W      = (const float*)d_in[7];
    const float* skip_film_W = (const float*)d_in[8];
    const float* skip_film_b = (const float*)d_in[9];
    const float* gat_W       = (const float*)d_in[10];
    const float* gat_att_src = (const float*)d_in[11];
    const float* gat_att_dst = (const float*)d_in[12];
    const float* gat_b       = (const float*)d_in[13];
    const float* lin_W       = (const float*)d_in[14];
    const float* lin_b       = (const float*)d_in[15];
    const float* fc_W        = (const float*)d_in[16];
    const float* fc_b        = (const float*)d_in[17];
    float* out = (float*)d_out;

    int n = in_sizes[0] / FIN;     // 50000
    int ne = in_sizes[2];          // 800000

    pack_kernel<<<64, 256>>>(skip_film_W, skip_W, film_lin_W, film_film_W,
                             film_film_b, skip_film_b, gat_W);
    zero_kernel<<<256, 256>>>();
    dim3 ggrid((n + 127) / 128, YW / 64);
    gemm_tc_kernel<<<ggrid, 256>>>(x, n);
    node_epi_kernel<<<(n + 7) / 8, 256>>>(n, gat_att_src, gat_att_dst);
    edge_p1_kernel<<<(ne + 255) / 256, 256>>>(ne, edge_index, edge_type);
    denom_kernel<<<(n + ne + 255) / 256, 256>>>(n, ne, edge_index);
    edge_p3_kernel<<<(ne + n + 7) / 8, 256>>>(n, ne, edge_index, edge_type);
    pool_kernel<<<(n + 7) / 8, 256>>>(n, graph_batch, gat_b);
    final_kernel<<<GG, 64>>>(lin_W, lin_b, fc_W, fc_b, out);
}

// round 5
// speedup vs baseline: 1.3954x; 1.1019x over previous
#include <cuda_runtime.h>
#include <cuda_bf16.h>
#include <cuda_fp16.h>
#include <math.h>

// Problem constants (fixed shapes per reference)
#define NN 50000
#define EE 800000
#define GG 64
#define FIN 64
#define HH 64
#define RR 3
#define CC 10
#define YW 832   // packed GEMM width
#define YH 640   // half-precision edge-accessed width (cols 192..832)

// Column layout in Wcat (GEMM output):
//  [0,128)   fs   = x @ skip_film_W + skip_film_b     -> d_Y192 fp32
//  [128,192) skip = x @ skip_W                        -> d_Y192 fp32
//  [192,384) xr   : r*64 + h  = x @ film_lin_W[r]     -> d_Yh fp16 (j-192)
//  [384,768) fm   : r*128 + c (beta c<64, gamma c>=64)-> d_Yh fp16
//  [768,832) xp   = x @ gat_W                         -> d_Yh fp16 (j=576..640)

// ---------------- scratch (device globals; no allocation allowed) -------------
__device__ float    d_Y192[(size_t)NN * 192];
__device__ __half   d_Yh[(size_t)NN * YH];
__device__ float    d_Wcat[64 * YW];
__device__ float    d_bcat[YW];
__device__ float    d_feats[(size_t)NN * 128];
__device__ float    d_as[NN];
__device__ float    d_ad[NN];
__device__ float    d_denomg[NN];
__device__ int      d_cnt[NN * RR];
__device__ int      d_poolmax[GG * 128];   // float bits, values >= 0
__device__ float    d_poolsum[GG * 128];
__device__ int      d_gcnt[GG];

// ---------------- helpers ----------------
__device__ __forceinline__ float lrelu(float x) { return x > 0.f ? x : 0.2f * x; }
__device__ __forceinline__ float frelu(float x) { return fmaxf(x, 0.f); }
__device__ __forceinline__ unsigned f2tf(float f) {
    unsigned u;
    asm("cvt.rna.tf32.f32 %0, %1;" : "=r"(u) : "f"(f));
    return u;
}
__device__ __forceinline__ void mma_tf32(float* d, const unsigned* a, const unsigned* b) {
    asm volatile(
        "mma.sync.aligned.m16n8k8.row.col.f32.tf32.tf32.f32 "
        "{%0,%1,%2,%3}, {%4,%5,%6,%7}, {%8,%9}, {%0,%1,%2,%3};"
        : "+f"(d[0]), "+f"(d[1]), "+f"(d[2]), "+f"(d[3])
        : "r"(a[0]), "r"(a[1]), "r"(a[2]), "r"(a[3]), "r"(b[0]), "r"(b[1]));
}
__device__ __forceinline__ void red_add_v4(float* p, float a, float b, float c, float d) {
    asm volatile("red.global.add.v4.f32 [%0], {%1,%2,%3,%4};"
                 :: "l"(p), "f"(a), "f"(b), "f"(c), "f"(d) : "memory");
}
// load 4 consecutive halves (8B aligned) as floats
__device__ __forceinline__ float4 ldh4(const __half* p) {
    uint2 u = *(const uint2*)p;
    __half2 a = *(__half2*)&u.x, b = *(__half2*)&u.y;
    float2 fa = __half22float2(a), fb = __half22float2(b);
    return make_float4(fa.x, fa.y, fb.x, fb.y);
}

// ---------------- 1. pack weights + biases ----------------
__global__ void pack_kernel(const float* __restrict__ skip_film_W,
                            const float* __restrict__ skip_W,
                            const float* __restrict__ film_lin_W,
                            const float* __restrict__ film_film_W,
                            const float* __restrict__ film_film_b,
                            const float* __restrict__ skip_film_b,
                            const float* __restrict__ gat_W) {
    int stride = blockDim.x * gridDim.x;
    for (int idx = blockIdx.x * blockDim.x + threadIdx.x; idx < 64 * YW; idx += stride) {
        int d = idx / YW, j = idx % YW;
        float v;
        if (j < 128)        v = skip_film_W[d * 128 + j];
        else if (j < 192)   v = skip_W[d * 64 + (j - 128)];
        else if (j < 384) { int r = (j - 192) >> 6, h = (j - 192) & 63;
                            v = film_lin_W[r * 4096 + d * 64 + h]; }
        else if (j < 768) { int r = (j - 384) >> 7, c = (j - 384) & 127;
                            v = film_film_W[r * 8192 + d * 128 + c]; }
        else                v = gat_W[d * 64 + (j - 768)];
        d_Wcat[idx] = v;
    }
    for (int j = blockIdx.x * blockDim.x + threadIdx.x; j < YW; j += stride) {
        float b = 0.f;
        if (j < 128)                 b = skip_film_b[j];
        else if (j >= 384 && j < 768) { int r = (j - 384) >> 7, c = (j - 384) & 127;
                                        b = film_film_b[r * 128 + c]; }
        d_bcat[j] = b;
    }
}

// ---------------- 2. zero scratch ----------------
__global__ void zero_kernel() {
    int stride = blockDim.x * gridDim.x;
    int t = blockIdx.x * blockDim.x + threadIdx.x;
    for (int i = t; i < NN * RR; i += stride) d_cnt[i] = 0;
    for (int i = t; i < GG * 128; i += stride) { d_poolmax[i] = 0; d_poolsum[i] = 0.f; }
    for (int i = t; i < GG; i += stride)      d_gcnt[i] = 0;
}

// ---------------- 3. tensor-core GEMM (3xTF32 split) ----------------
// Block tile: M=128, N=64, K=64 (full). 256 threads = 8 warps (4m x 2n),
// each warp computes a 32x32 tile = 2 (m16) x 4 (n8) mma fragments.
__global__ __launch_bounds__(256) void gemm_tc_kernel(const float* __restrict__ A, int n) {
    __shared__ float As[128][68];
    __shared__ float Bs[64][72];
    int row0 = blockIdx.x * 128;
    int col0 = blockIdx.y * 64;
    int tid = threadIdx.x;

    #pragma unroll
    for (int i = 0; i < 8; i++) {
        int e = i * 256 + tid;
        int r = e >> 4;
        int c4 = (e & 15) << 2;
        float4 v = make_float4(0.f, 0.f, 0.f, 0.f);
        if (row0 + r < n) v = *(const float4*)(A + (size_t)(row0 + r) * 64 + c4);
        As[r][c4] = v.x; As[r][c4 + 1] = v.y; As[r][c4 + 2] = v.z; As[r][c4 + 3] = v.w;
    }
    #pragma unroll
    for (int i = 0; i < 4; i++) {
        int e = i * 256 + tid;
        int k = e >> 4;
        int c4 = (e & 15) << 2;
        float4 v = *(const float4*)(d_Wcat + k * YW + col0 + c4);
        Bs[k][c4] = v.x; Bs[k][c4 + 1] = v.y; Bs[k][c4 + 2] = v.z; Bs[k][c4 + 3] = v.w;
    }
    __syncthreads();

    int warp = tid >> 5, lane = tid & 31;
    int wm = (warp >> 1) * 32;
    int wn = (warp & 1) * 32;
    int lr = lane >> 2;
    int lc = lane & 3;

    float acc[2][4][4] = {};
    #pragma unroll
    for (int k0 = 0; k0 < 64; k0 += 8) {
        unsigned abig[2][4], asml[2][4];
        #pragma unroll
        for (int mi = 0; mi < 2; mi++) {
            int r = wm + mi * 16 + lr;
            float a0 = As[r][k0 + lc];
            float a1 = As[r + 8][k0 + lc];
            float a2 = As[r][k0 + 4 + lc];
            float a3 = As[r + 8][k0 + 4 + lc];
            abig[mi][0] = f2tf(a0); asml[mi][0] = f2tf(a0 - __uint_as_float(abig[mi][0]));
            abig[mi][1] = f2tf(a1); asml[mi][1] = f2tf(a1 - __uint_as_float(abig[mi][1]));
            abig[mi][2] = f2tf(a2); asml[mi][2] = f2tf(a2 - __uint_as_float(abig[mi][2]));
            abig[mi][3] = f2tf(a3); asml[mi][3] = f2tf(a3 - __uint_as_float(abig[mi][3]));
        }
        unsigned bbig[4][2], bsml[4][2];
        #pragma unroll
        for (int ni = 0; ni < 4; ni++) {
            int c = wn + ni * 8 + lr;
            float b0 = Bs[k0 + lc][c];
            float b1 = Bs[k0 + 4 + lc][c];
            bbig[ni][0] = f2tf(b0); bsml[ni][0] = f2tf(b0 - __uint_as_float(bbig[ni][0]));
            bbig[ni][1] = f2tf(b1); bsml[ni][1] = f2tf(b1 - __uint_as_float(bbig[ni][1]));
        }
        #pragma unroll
        for (int mi = 0; mi < 2; mi++)
            #pragma unroll
            for (int ni = 0; ni < 4; ni++) {
                mma_tf32(acc[mi][ni], abig[mi], bbig[ni]);
                mma_tf32(acc[mi][ni], abig[mi], bsml[ni]);
                mma_tf32(acc[mi][ni], asml[mi], bbig[ni]);
            }
    }

    // epilogue: bias + store; cols <192 -> fp32 d_Y192, cols >=192 -> fp16 d_Yh
    bool is_half = (col0 >= 192);   // uniform per block (192 = 3*64)
    #pragma unroll
    for (int mi = 0; mi < 2; mi++) {
        #pragma unroll
        for (int ni = 0; ni < 4; ni++) {
            int c = col0 + wn + ni * 8 + 2 * lc;
            float b0 = d_bcat[c], b1 = d_bcat[c + 1];
            int r0 = row0 + wm + mi * 16 + lr;
            #pragma unroll
            for (int rr = 0; rr < 2; rr++) {
                int r = r0 + rr * 8;
                if (r >= n) continue;
                float v0 = acc[mi][ni][rr * 2] + b0;
                float v1 = acc[mi][ni][rr * 2 + 1] + b1;
                if (is_half) {
                    *(__half2*)(d_Yh + (size_t)r * YH + (c - 192)) = __floats2half2_rn(v0, v1);
                } else {
                    *(float2*)(d_Y192 + (size_t)r * 192 + c) = make_float2(v0, v1);
                }
            }
        }
    }
}

// ---------------- 4. node epilogue: skip path, alpha dots, denom seed ----------
__global__ void node_epi_kernel(int n, const float* __restrict__ att_src,
                                const float* __restrict__ att_dst) {
    int w = (blockIdx.x * blockDim.x + threadIdx.x) >> 5;
    int l = threadIdx.x & 31;
    if (w >= n) return;
    const float* yr = d_Y192 + (size_t)w * 192;
    float* fr = d_feats + (size_t)w * 128;
    #pragma unroll
    for (int p = 0; p < 2; p++) {
        int h = l + p * 32;
        float f0 = yr[h], mul = yr[64 + h], sk = yr[128 + h];
        fr[h] = frelu(mul * sk + f0);    // FiLM skip path (pre-agg)
        fr[64 + h] = 0.f;                // GAT accumulator
    }
    const __half* xph = d_Yh + (size_t)w * YH + 576;
    float xp0 = __half2float(xph[l]), xp1 = __half2float(xph[l + 32]);
    float ps = xp0 * att_src[l] + xp1 * att_src[l + 32];
    float pd = xp0 * att_dst[l] + xp1 * att_dst[l + 32];
    #pragma unroll
    for (int off = 16; off > 0; off >>= 1) {
        ps += __shfl_down_sync(0xffffffffu, ps, off);
        pd += __shfl_down_sync(0xffffffffu, pd, off);
    }
    if (l == 0) {
        d_as[w] = ps;
        d_ad[w] = pd;
        d_denomg[w] = expf(lrelu(ps + pd));   // self-loop seeds the denominator
    }
}

// ---------------- 5. fused edge pass: counts + GAT softmax denominator --------
// (no max-shift: e = lrelu(as+ad) has |e| << 80, exp(e) cannot overflow)
__global__ void edge_cd_kernel(int ne, const int* __restrict__ ei,
                               const int* __restrict__ et) {
    int e = blockIdx.x * blockDim.x + threadIdx.x;
    if (e >= ne) return;
    int s = ei[e], d = ei[ne + e], t = et[e];
    atomicAdd(&d_cnt[d * RR + t], 1);
    atomicAdd(&d_denomg[d], expf(lrelu(d_as[s] + d_ad[d])));
}

// ---------------- 6. fused vector pass: FiLM messages + GAT gather ------------
// warp per edge; lanes 0-15: FiLM (4 h each); lanes 16-31: GAT (4 h each).
__global__ void edge_p3_kernel(int ne, const int* __restrict__ ei,
                               const int* __restrict__ et) {
    int w = (blockIdx.x * blockDim.x + threadIdx.x) >> 5;
    int l = threadIdx.x & 31;
    if (w >= ne) return;
    int s = ei[w], d = ei[ne + w], t = et[w];
    float* fd = d_feats + (size_t)d * 128;
    if (l < 16) {
        int h = l << 2;
        float rdn = 1.f / fmaxf((float)d_cnt[d * RR + t], 1.f);
        const __half* gB = d_Yh + (size_t)d * YH + 192 + t * 128;  // beta[h], gamma[64+h]
        const __half* xr = d_Yh + (size_t)s * YH + t * 64;
        float4 beta = ldh4(gB + h);
        float4 gamm = ldh4(gB + 64 + h);
        float4 xv   = ldh4(xr + h);
        red_add_v4(fd + h,
                   frelu(gamm.x * xv.x + beta.x) * rdn,
                   frelu(gamm.y * xv.y + beta.y) * rdn,
                   frelu(gamm.z * xv.z + beta.z) * rdn,
                   frelu(gamm.w * xv.w + beta.w) * rdn);
    } else {
        int h = (l - 16) << 2;
        float wgt = expf(lrelu(d_as[s] + d_ad[d])) / d_denomg[d];
        float4 xv = ldh4(d_Yh + (size_t)s * YH + 576 + h);
        red_add_v4(fd + 64 + h, wgt * xv.x, wgt * xv.y, wgt * xv.z, wgt * xv.w);
    }
}

// ---------------- 7. per-graph pooling (+ GAT self-loop term) -----------------
__global__ void pool_kernel(int n, const int* __restrict__ gb,
                            const float* __restrict__ gat_b) {
    int w = (blockIdx.x * blockDim.x + threadIdx.x) >> 5;
    int l = threadIdx.x & 31;
    if (w >= n) return;
    int g = gb[w];
    const float* fr = d_feats + (size_t)w * 128;
    float wgt = expf(lrelu(d_as[w] + d_ad[w])) / d_denomg[w];   // self-loop alpha
    const __half* xph = d_Yh + (size_t)w * YH + 576;
    #pragma unroll
    for (int p = 0; p < 4; p++) {
        int j = l + p * 32;
        float v = fr[j];
        if (j < 64) v = frelu(v);
        else        v = frelu(v + wgt * __half2float(xph[j - 64]) + gat_b[j - 64]);
        atomicMax(&d_poolmax[g * 128 + j], __float_as_int(v));  // v >= 0
        atomicAdd(&d_poolsum[g * 128 + j], v);
    }
    if (l == 0) atomicAdd(&d_gcnt[g], 1);
}

// ---------------- 8. final MLP + log_softmax ----------------
__global__ void final_kernel(const float* __restrict__ lin_W, const float* __restrict__ lin_b,
                             const float* __restrict__ fc_W, const float* __restrict__ fc_b,
                             float* __restrict__ out) {
    int g = blockIdx.x, t = threadIdx.x;   // 64 threads
    __shared__ float pooled[256];
    __shared__ float hid[64];
    __shared__ float logits[CC];
    __shared__ float mx, lse;
    float cm = fmaxf((float)d_gcnt[g], 1.f);
    for (int j = t; j < 128; j += 64) {
        pooled[j] = __int_as_float(d_poolmax[g * 128 + j]);
        pooled[128 + j] = d_poolsum[g * 128 + j] / cm;
    }
    __syncthreads();
    float hs = lin_b[t];
    #pragma unroll 4
    for (int k = 0; k < 256; k++) hs = fmaf(pooled[k], lin_W[k * 64 + t], hs);
    hid[t] = frelu(hs);
    __syncthreads();
    if (t < CC) {
        float s = fc_b[t];
        #pragma unroll
        for (int h = 0; h < 64; h++) s = fmaf(hid[h], fc_W[h * CC + t], s);
        logits[t] = s;
    }
    __syncthreads();
    if (t == 0) {
        float m = logits[0];
        #pragma unroll
        for (int c = 1; c < CC; c++) m = fmaxf(m, logits[c]);
        float sum = 0.f;
        #pragma unroll
        for (int c = 0; c < CC; c++) sum += expf(logits[c] - m);
        mx = m; lse = logf(sum);
    }
    __syncthreads();
    if (t < CC) out[g * CC + t] = logits[t] - mx - lse;
}

// ---------------- launch ----------------
extern "C" void kernel_launch(void* const* d_in, const int* in_sizes, int n_in,
                              void* d_out, int out_size) {
    const float* x           = (const float*)d_in[0];
    const int*   edge_index  = (const int*)d_in[1];
    const int*   edge_type   = (const int*)d_in[2];
    const int*   graph_batch = (const int*)d_in[3];
    const float* film_lin_W  = (const float*)d_in[4];
    const float* film_film_W = (const float*)d_in[5];
    const float* film_film_b = (const float*)d_in[6];
    const float* skip_W      = (const float*)d_in[7];
    const float* skip_film_W = (const float*)d_in[8];
    const float* skip_film_b = (const float*)d_in[9];
    const float* gat_W       = (const float*)d_in[10];
    const float* gat_att_src = (const float*)d_in[11];
    const float* gat_att_dst = (const float*)d_in[12];
    const float* gat_b       = (const float*)d_in[13];
    const float* lin_W       = (const float*)d_in[14];
    const float* lin_b       = (const float*)d_in[15];
    const float* fc_W        = (const float*)d_in[16];
    const float* fc_b        = (const float*)d_in[17];
    float* out = (float*)d_out;

    int n = in_sizes[0] / FIN;     // 50000
    int ne = in_sizes[2];          // 800000

    pack_kernel<<<64, 256>>>(skip_film_W, skip_W, film_lin_W, film_film_W,
                             film_film_b, skip_film_b, gat_W);
    zero_kernel<<<256, 256>>>();
    dim3 ggrid((n + 127) / 128, YW / 64);
    gemm_tc_kernel<<<ggrid, 256>>>(x, n);
    node_epi_kernel<<<(n + 7) / 8, 256>>>(n, gat_att_src, gat_att_dst);
    edge_cd_kernel<<<(ne + 255) / 256, 256>>>(ne, edge_index, edge_type);
    edge_p3_kernel<<<(ne + 7) / 8, 256>>>(ne, edge_index, edge_type);
    pool_kernel<<<(n + 7) / 8, 256>>>(n, graph_batch, gat_b);
    final_kernel<<<GG, 64>>>(lin_W, lin_b, fc_W, fc_b, out);
}

// round 7
// speedup vs baseline: 1.5172x; 1.0873x over previous
#include <cuda_runtime.h>
#include <cuda_bf16.h>
#include <cuda_fp16.h>
#include <math.h>

// Problem constants (fixed shapes per reference)
#define NN 50000
#define EE 800000
#define GG 64
#define FIN 64
#define HH 64
#define RR 3
#define CC 10
#define YW 832   // packed GEMM width
#define YH 640   // half-precision edge-accessed width (cols 192..832)

// Column layout in Wcat (GEMM output):
//  [0,128)   fs   = x @ skip_film_W + skip_film_b     -> d_Y192 fp32
//  [128,192) skip = x @ skip_W                        -> d_Y192 fp32
//  [192,384) xr   : r*64 + h  = x @ film_lin_W[r]     -> d_Yh fp16 (col j-192)
//  [384,768) fm   : r*128 + c (beta c<64, gamma c>=64)-> d_Yh fp16
//  [768,832) xp   = x @ gat_W                         -> d_Yh fp16 (cols 576..640)

// ---------------- scratch (device globals; no allocation allowed) -------------
__device__ float    d_Y192[(size_t)NN * 192];
__device__ __half   d_Yh[(size_t)NN * YH];
__device__ float    d_Wcat[64 * YW];
__device__ float    d_bcat[YW];
__device__ float    d_as[NN];
__device__ float    d_ad[NN];
__device__ int      d_hist[NN];
__device__ int      d_segoff[NN + 1];
__device__ int      d_cursor[NN];
__device__ int      d_sorted[EE];          // src | (type<<16)  (src < 65536)
__device__ int      d_poolmax[GG * 128];   // float bits, values >= 0
__device__ float    d_poolsum[GG * 128];
__device__ int      d_gcnt[GG];

// ---------------- helpers ----------------
__device__ __forceinline__ float lrelu(float x) { return x > 0.f ? x : 0.2f * x; }
__device__ __forceinline__ float frelu(float x) { return fmaxf(x, 0.f); }
__device__ __forceinline__ unsigned f2tf(float f) {
    unsigned u;
    asm("cvt.rna.tf32.f32 %0, %1;" : "=r"(u) : "f"(f));
    return u;
}
__device__ __forceinline__ void mma_tf32(float* d, const unsigned* a, const unsigned* b) {
    asm volatile(
        "mma.sync.aligned.m16n8k8.row.col.f32.tf32.tf32.f32 "
        "{%0,%1,%2,%3}, {%4,%5,%6,%7}, {%8,%9}, {%0,%1,%2,%3};"
        : "+f"(d[0]), "+f"(d[1]), "+f"(d[2]), "+f"(d[3])
        : "r"(a[0]), "r"(a[1]), "r"(a[2]), "r"(a[3]), "r"(b[0]), "r"(b[1]));
}
__device__ __forceinline__ float2 ldh2(const __half* p) {
    return __half22float2(*(const __half2*)p);
}

// ---------------- 1. pack weights + biases ----------------
__global__ void pack_kernel(const float* __restrict__ skip_film_W,
                            const float* __restrict__ skip_W,
                            const float* __restrict__ film_lin_W,
                            const float* __restrict__ film_film_W,
                            const float* __restrict__ film_film_b,
                            const float* __restrict__ skip_film_b,
                            const float* __restrict__ gat_W) {
    int stride = blockDim.x * gridDim.x;
    for (int idx = blockIdx.x * blockDim.x + threadIdx.x; idx < 64 * YW; idx += stride) {
        int d = idx / YW, j = idx % YW;
        float v;
        if (j < 128)        v = skip_film_W[d * 128 + j];
        else if (j < 192)   v = skip_W[d * 64 + (j - 128)];
        else if (j < 384) { int r = (j - 192) >> 6, h = (j - 192) & 63;
                            v = film_lin_W[r * 4096 + d * 64 + h]; }
        else if (j < 768) { int r = (j - 384) >> 7, c = (j - 384) & 127;
                            v = film_film_W[r * 8192 + d * 128 + c]; }
        else                v = gat_W[d * 64 + (j - 768)];
        d_Wcat[idx] = v;
    }
    for (int j = blockIdx.x * blockDim.x + threadIdx.x; j < YW; j += stride) {
        float b = 0.f;
        if (j < 128)                 b = skip_film_b[j];
        else if (j >= 384 && j < 768) { int r = (j - 384) >> 7, c = (j - 384) & 127;
                                        b = film_film_b[r * 128 + c]; }
        d_bcat[j] = b;
    }
}

// ---------------- 2. zero scratch ----------------
__global__ void zero_kernel() {
    int stride = blockDim.x * gridDim.x;
    int t = blockIdx.x * blockDim.x + threadIdx.x;
    for (int i = t; i < NN; i += stride) { d_hist[i] = 0; d_cursor[i] = 0; }
    for (int i = t; i < GG * 128; i += stride) { d_poolmax[i] = 0; d_poolsum[i] = 0.f; }
    for (int i = t; i < GG; i += stride)      d_gcnt[i] = 0;
}

// ---------------- 3. tensor-core GEMM (3xTF32 split) ----------------
__global__ __launch_bounds__(256) void gemm_tc_kernel(const float* __restrict__ A, int n) {
    __shared__ float As[128][68];
    __shared__ float Bs[64][72];
    int row0 = blockIdx.x * 128;
    int col0 = blockIdx.y * 64;
    int tid = threadIdx.x;

    #pragma unroll
    for (int i = 0; i < 8; i++) {
        int e = i * 256 + tid;
        int r = e >> 4;
        int c4 = (e & 15) << 2;
        float4 v = make_float4(0.f, 0.f, 0.f, 0.f);
        if (row0 + r < n) v = *(const float4*)(A + (size_t)(row0 + r) * 64 + c4);
        As[r][c4] = v.x; As[r][c4 + 1] = v.y; As[r][c4 + 2] = v.z; As[r][c4 + 3] = v.w;
    }
    #pragma unroll
    for (int i = 0; i < 4; i++) {
        int e = i * 256 + tid;
        int k = e >> 4;
        int c4 = (e & 15) << 2;
        float4 v = *(const float4*)(d_Wcat + k * YW + col0 + c4);
        Bs[k][c4] = v.x; Bs[k][c4 + 1] = v.y; Bs[k][c4 + 2] = v.z; Bs[k][c4 + 3] = v.w;
    }
    __syncthreads();

    int warp = tid >> 5, lane = tid & 31;
    int wm = (warp >> 1) * 32;
    int wn = (warp & 1) * 32;
    int lr = lane >> 2;
    int lc = lane & 3;

    float acc[2][4][4] = {};
    #pragma unroll
    for (int k0 = 0; k0 < 64; k0 += 8) {
        unsigned abig[2][4], asml[2][4];
        #pragma unroll
        for (int mi = 0; mi < 2; mi++) {
            int r = wm + mi * 16 + lr;
            float a0 = As[r][k0 + lc];
            float a1 = As[r + 8][k0 + lc];
            float a2 = As[r][k0 + 4 + lc];
            float a3 = As[r + 8][k0 + 4 + lc];
            abig[mi][0] = f2tf(a0); asml[mi][0] = f2tf(a0 - __uint_as_float(abig[mi][0]));
            abig[mi][1] = f2tf(a1); asml[mi][1] = f2tf(a1 - __uint_as_float(abig[mi][1]));
            abig[mi][2] = f2tf(a2); asml[mi][2] = f2tf(a2 - __uint_as_float(abig[mi][2]));
            abig[mi][3] = f2tf(a3); asml[mi][3] = f2tf(a3 - __uint_as_float(abig[mi][3]));
        }
        unsigned bbig[4][2], bsml[4][2];
        #pragma unroll
        for (int ni = 0; ni < 4; ni++) {
            int c = wn + ni * 8 + lr;
            float b0 = Bs[k0 + lc][c];
            float b1 = Bs[k0 + 4 + lc][c];
            bbig[ni][0] = f2tf(b0); bsml[ni][0] = f2tf(b0 - __uint_as_float(bbig[ni][0]));
            bbig[ni][1] = f2tf(b1); bsml[ni][1] = f2tf(b1 - __uint_as_float(bbig[ni][1]));
        }
        #pragma unroll
        for (int mi = 0; mi < 2; mi++)
            #pragma unroll
            for (int ni = 0; ni < 4; ni++) {
                mma_tf32(acc[mi][ni], abig[mi], bbig[ni]);
                mma_tf32(acc[mi][ni], abig[mi], bsml[ni]);
                mma_tf32(acc[mi][ni], asml[mi], bbig[ni]);
            }
    }

    bool is_half = (col0 >= 192);   // uniform per block
    #pragma unroll
    for (int mi = 0; mi < 2; mi++) {
        #pragma unroll
        for (int ni = 0; ni < 4; ni++) {
            int c = col0 + wn + ni * 8 + 2 * lc;
            float b0 = d_bcat[c], b1 = d_bcat[c + 1];
            int r0 = row0 + wm + mi * 16 + lr;
            #pragma unroll
            for (int rr = 0; rr < 2; rr++) {
                int r = r0 + rr * 8;
                if (r >= n) continue;
                float v0 = acc[mi][ni][rr * 2] + b0;
                float v1 = acc[mi][ni][rr * 2 + 1] + b1;
                if (is_half) {
                    *(__half2*)(d_Yh + (size_t)r * YH + (c - 192)) = __floats2half2_rn(v0, v1);
                } else {
                    *(float2*)(d_Y192 + (size_t)r * 192 + c) = make_float2(v0, v1);
                }
            }
        }
    }
}

// ---------------- 4. node epilogue: attention dot products --------------------
__global__ void node_epi_kernel(int n, const float* __restrict__ att_src,
                                const float* __restrict__ att_dst) {
    int w = (blockIdx.x * blockDim.x + threadIdx.x) >> 5;
    int l = threadIdx.x & 31;
    if (w >= n) return;
    const __half* xph = d_Yh + (size_t)w * YH + 576;
    float xp0 = __half2float(xph[l]), xp1 = __half2float(xph[l + 32]);
    float ps = xp0 * att_src[l] + xp1 * att_src[l + 32];
    float pd = xp0 * att_dst[l] + xp1 * att_dst[l + 32];
    #pragma unroll
    for (int off = 16; off > 0; off >>= 1) {
        ps += __shfl_down_sync(0xffffffffu, ps, off);
        pd += __shfl_down_sync(0xffffffffu, pd, off);
    }
    if (l == 0) { d_as[w] = ps; d_ad[w] = pd; }
}

// ---------------- 5. counting sort of edges by dst ----------------------------
__global__ void hist_kernel(int ne, const int* __restrict__ ei) {
    int e = blockIdx.x * blockDim.x + threadIdx.x;
    if (e >= ne) return;
    atomicAdd(&d_hist[ei[ne + e]], 1);
}

// single-block exclusive scan over d_hist -> d_segoff (NN+1 entries)
__global__ void scan_kernel() {
    __shared__ int warp_tot[32];
    __shared__ int s_carry;
    int tid = threadIdx.x, lane = tid & 31, wid = tid >> 5;
    if (tid == 0) s_carry = 0;
    __syncthreads();
    for (int base = 0; base < NN; base += 1024) {
        int i = base + tid;
        int v = (i < NN) ? d_hist[i] : 0;
        int x = v;
        #pragma unroll
        for (int o = 1; o < 32; o <<= 1) {
            int y = __shfl_up_sync(0xffffffffu, x, o);
            if (lane >= o) x += y;
        }
        if (lane == 31) warp_tot[wid] = x;
        __syncthreads();
        if (wid == 0) {
            int w = warp_tot[lane];
            #pragma unroll
            for (int o = 1; o < 32; o <<= 1) {
                int y = __shfl_up_sync(0xffffffffu, w, o);
                if (lane >= o) w += y;
            }
            warp_tot[lane] = w;
        }
        __syncthreads();
        int incl = x + (wid > 0 ? warp_tot[wid - 1] : 0);
        if (i < NN) d_segoff[i] = s_carry + incl - v;
        __syncthreads();
        if (tid == 1023) s_carry += incl;   // incl of last thread = chunk total
        __syncthreads();
    }
    if (tid == 0) d_segoff[NN] = s_carry;
}

__global__ void scatter_kernel(int ne, const int* __restrict__ ei,
                               const int* __restrict__ et) {
    int e = blockIdx.x * blockDim.x + threadIdx.x;
    if (e >= ne) return;
    int s = ei[e], d = ei[ne + e], t = et[e];
    int pos = d_segoff[d] + atomicAdd(&d_cursor[d], 1);
    d_sorted[pos] = s | (t << 16);
}

// ---------------- 6. fused aggregation + pooling: one warp per dst ------------
// Each lane owns h = {2l, 2l+1}. Atomic-free FiLM/GAT aggregation in registers;
// pooling atomics at the end. exp(e) computed once per edge on the owning lane
// during the load phase, then broadcast (1 MUFU warp-op per 32-edge batch).
__global__ __launch_bounds__(256) void agg_kernel(int n, const int* __restrict__ gb,
                                                  const float* __restrict__ gat_b) {
    int d = (blockIdx.x * blockDim.x + threadIdx.x) >> 5;
    int l = threadIdx.x & 31;
    if (d >= n) return;

    const __half* yh_d = d_Yh + (size_t)d * YH;
    // beta/gamma for the 3 relation types at this dst (fm block: cols 192..576)
    float2 be0 = ldh2(yh_d + 192 + 0 * 128 + 2 * l);
    float2 ga0 = ldh2(yh_d + 192 + 0 * 128 + 64 + 2 * l);
    float2 be1 = ldh2(yh_d + 192 + 1 * 128 + 2 * l);
    float2 ga1 = ldh2(yh_d + 192 + 1 * 128 + 64 + 2 * l);
    float2 be2 = ldh2(yh_d + 192 + 2 * 128 + 2 * l);
    float2 ga2 = ldh2(yh_d + 192 + 2 * 128 + 64 + 2 * l);

    float f0x = 0.f, f0y = 0.f, f1x = 0.f, f1y = 0.f, f2x = 0.f, f2y = 0.f;
    float gx = 0.f, gy = 0.f;
    float denom = 0.f;
    int c0 = 0, c1 = 0, c2 = 0;
    float ad_d = d_ad[d];

    int beg = d_segoff[d], end = d_segoff[d + 1];
    for (int base = beg; base < end; base += 32) {
        int i = base + l;
        int pk = 0; float ex = 0.f;
        if (i < end) {
            pk = d_sorted[i];
            ex = expf(lrelu(d_as[pk & 0xFFFF] + ad_d));
        }
        int m = min(32, end - base);
        for (int j = 0; j < m; j++) {
            int pkj  = __shfl_sync(0xffffffffu, pk, j);
            float exj = __shfl_sync(0xffffffffu, ex, j);
            int s = pkj & 0xFFFF, t = pkj >> 16;
            denom += exj;
            const __half* yh_s = d_Yh + (size_t)s * YH;
            float2 xp = ldh2(yh_s + 576 + 2 * l);
            gx += exj * xp.x; gy += exj * xp.y;
            // warp-uniform branch on t (no divergence, keeps accs in registers)
            if (t == 0) {
                float2 xr = ldh2(yh_s + 0 * 64 + 2 * l);
                f0x += frelu(ga0.x * xr.x + be0.x);
                f0y += frelu(ga0.y * xr.y + be0.y);
                c0++;
            } else if (t == 1) {
                float2 xr = ldh2(yh_s + 1 * 64 + 2 * l);
                f1x += frelu(ga1.x * xr.x + be1.x);
                f1y += frelu(ga1.y * xr.y + be1.y);
                c1++;
            } else {
                float2 xr = ldh2(yh_s + 2 * 64 + 2 * l);
                f2x += frelu(ga2.x * xr.x + be2.x);
                f2y += frelu(ga2.y * xr.y + be2.y);
                c2++;
            }
        }
    }

    // GAT self loop
    float ex_self = expf(lrelu(d_as[d] + ad_d));
    denom += ex_self;
    float2 xp_d = ldh2(yh_d + 576 + 2 * l);
    gx += ex_self * xp_d.x; gy += ex_self * xp_d.y;
    float rden = 1.f / denom;

    float r0 = 1.f / fmaxf((float)c0, 1.f);
    float r1 = 1.f / fmaxf((float)c1, 1.f);
    float r2 = 1.f / fmaxf((float)c2, 1.f);
    float filmx = f0x * r0 + f1x * r1 + f2x * r2;
    float filmy = f0y * r0 + f1y * r1 + f2y * r2;

    // FiLM skip path from fp32 block
    const float* yr = d_Y192 + (size_t)d * 192;
    float2 fsb = *(const float2*)(yr + 2 * l);         // fs beta
    float2 fsg = *(const float2*)(yr + 64 + 2 * l);    // fs gamma
    float2 skv = *(const float2*)(yr + 128 + 2 * l);   // x @ skip_W
    float v1x = frelu(frelu(fsg.x * skv.x + fsb.x) + filmx);
    float v1y = frelu(frelu(fsg.y * skv.y + fsb.y) + filmy);

    float v2x = frelu(gx * rden + gat_b[2 * l]);
    float v2y = frelu(gy * rden + gat_b[2 * l + 1]);

    // pooling
    int g = __shfl_sync(0xffffffffu, (l == 0) ? gb[d] : 0, 0);
    int pbase = g * 128 + 2 * l;
    atomicMax(&d_poolmax[pbase],     __float_as_int(v1x));
    atomicMax(&d_poolmax[pbase + 1], __float_as_int(v1y));
    atomicMax(&d_poolmax[pbase + 64],     __float_as_int(v2x));
    atomicMax(&d_poolmax[pbase + 65], __float_as_int(v2y));
    atomicAdd(&d_poolsum[pbase],     v1x);
    atomicAdd(&d_poolsum[pbase + 1], v1y);
    atomicAdd(&d_poolsum[pbase + 64],     v2x);
    atomicAdd(&d_poolsum[pbase + 65], v2y);
    if (l == 0) atomicAdd(&d_gcnt[g], 1);
}

// ---------------- 7. final MLP + log_softmax ----------------
__global__ void final_kernel(const float* __restrict__ lin_W, const float* __restrict__ lin_b,
                             const float* __restrict__ fc_W, const float* __restrict__ fc_b,
                             float* __restrict__ out) {
    int g = blockIdx.x, t = threadIdx.x;   // 64 threads
    __shared__ float pooled[256];
    __shared__ float hid[64];
    __shared__ float logits[CC];
    __shared__ float mx, lse;
    float cm = fmaxf((float)d_gcnt[g], 1.f);
    for (int j = t; j < 128; j += 64) {
        pooled[j] = __int_as_float(d_poolmax[g * 128 + j]);
        pooled[128 + j] = d_poolsum[g * 128 + j] / cm;
    }
    __syncthreads();
    float hs = lin_b[t];
    #pragma unroll 4
    for (int k = 0; k < 256; k++) hs = fmaf(pooled[k], lin_W[k * 64 + t], hs);
    hid[t] = frelu(hs);
    __syncthreads();
    if (t < CC) {
        float s = fc_b[t];
        #pragma unroll
        for (int h = 0; h < 64; h++) s = fmaf(hid[h], fc_W[h * CC + t], s);
        logits[t] = s;
    }
    __syncthreads();
    if (t == 0) {
        float m = logits[0];
        #pragma unroll
        for (int c = 1; c < CC; c++) m = fmaxf(m, logits[c]);
        float sum = 0.f;
        #pragma unroll
        for (int c = 0; c < CC; c++) sum += expf(logits[c] - m);
        mx = m; lse = logf(sum);
    }
    __syncthreads();
    if (t < CC) out[g * CC + t] = logits[t] - mx - lse;
}

// ---------------- launch ----------------
extern "C" void kernel_launch(void* const* d_in, const int* in_sizes, int n_in,
                              void* d_out, int out_size) {
    const float* x           = (const float*)d_in[0];
    const int*   edge_index  = (const int*)d_in[1];
    const int*   edge_type   = (const int*)d_in[2];
    const int*   graph_batch = (const int*)d_in[3];
    const float* film_lin_W  = (const float*)d_in[4];
    const float* film_film_W = (const float*)d_in[5];
    const float* film_film_b = (const float*)d_in[6];
    const float* skip_W      = (const float*)d_in[7];
    const float* skip_film_W = (const float*)d_in[8];
    const float* skip_film_b = (const float*)d_in[9];
    const float* gat_W       = (const float*)d_in[10];
    const float* gat_att_src = (const float*)d_in[11];
    const float* gat_att_dst = (const float*)d_in[12];
    const float* gat_b       = (const float*)d_in[13];
    const float* lin_W       = (const float*)d_in[14];
    const float* lin_b       = (const float*)d_in[15];
    const float* fc_W        = (const float*)d_in[16];
    const float* fc_b        = (const float*)d_in[17];
    float* out = (float*)d_out;

    int n = in_sizes[0] / FIN;     // 50000
    int ne = in_sizes[2];          // 800000

    pack_kernel<<<64, 256>>>(skip_film_W, skip_W, film_lin_W, film_film_W,
                             film_film_b, skip_film_b, gat_W);
    zero_kernel<<<256, 256>>>();
    hist_kernel<<<(ne + 255) / 256, 256>>>(ne, edge_index);
    scan_kernel<<<1, 1024>>>();
    scatter_kernel<<<(ne + 255) / 256, 256>>>(ne, edge_index, edge_type);
    dim3 ggrid((n + 127) / 128, YW / 64);
    gemm_tc_kernel<<<ggrid, 256>>>(x, n);
    node_epi_kernel<<<(n + 7) / 8, 256>>>(n, gat_att_src, gat_att_dst);
    agg_kernel<<<(n + 7) / 8, 256>>>(n, graph_batch, gat_b);
    final_kernel<<<GG, 64>>>(lin_W, lin_b, fc_W, fc_b, out);
}

// round 8
// speedup vs baseline: 1.7094x; 1.1267x over previous
#include <cuda_runtime.h>
#include <cuda_bf16.h>
#include <cuda_fp16.h>
#include <math.h>

// Problem constants (fixed shapes per reference)
#define NN 50000
#define EE 800000
#define GG 64
#define FIN 64
#define HH 64
#define RR 3
#define CC 10
#define YW 832   // packed GEMM width
#define YH 640   // half-precision edge-accessed width (cols 192..832)
#define SCAN_B 1024
#define SCAN_NB ((NN + SCAN_B - 1) / SCAN_B)   // 49

// Column layout in Wcat (GEMM output):
//  [0,128)   fs   = x @ skip_film_W + skip_film_b     -> d_Y192 fp32
//  [128,192) skip = x @ skip_W                        -> d_Y192 fp32
//  [192,384) xr   : r*64 + h  = x @ film_lin_W[r]     -> d_Yh fp16 (col j-192)
//  [384,768) fm   : r*128 + c (beta c<64, gamma c>=64)-> d_Yh fp16
//  [768,832) xp   = x @ gat_W                         -> d_Yh fp16 (cols 576..640)

// ---------------- scratch (device globals; no allocation allowed) -------------
__device__ float    d_Y192[(size_t)NN * 192];
__device__ __half   d_Yh[(size_t)NN * YH];
__device__ float    d_Wcat[64 * YW];
__device__ float    d_bcat[YW];
__device__ float    d_as[NN];
__device__ float    d_ad[NN];
__device__ int      d_hist[NN];
__device__ int      d_segoff[NN + 1];
__device__ int      d_cursor[NN];
__device__ int      d_blksum[SCAN_NB];
__device__ int      d_blkoff[SCAN_NB];
__device__ int      d_sorted[EE];          // src | (type<<16)  (src < 65536)
__device__ int      d_poolmax[GG * 128];   // float bits, values >= 0
__device__ float    d_poolsum[GG * 128];
__device__ int      d_gcnt[GG];

// ---------------- streams/events for fork-join inside graph capture -----------
static cudaStream_t g_s2;
static cudaEvent_t  g_evFork, g_evJoin;
struct _StreamInit {
    _StreamInit() {
        cudaStreamCreateWithFlags(&g_s2, cudaStreamNonBlocking);
        cudaEventCreateWithFlags(&g_evFork, cudaEventDisableTiming);
        cudaEventCreateWithFlags(&g_evJoin, cudaEventDisableTiming);
    }
};
static _StreamInit g_streamInit;

// ---------------- helpers ----------------
__device__ __forceinline__ float lrelu(float x) { return x > 0.f ? x : 0.2f * x; }
__device__ __forceinline__ float frelu(float x) { return fmaxf(x, 0.f); }
__device__ __forceinline__ unsigned f2tf(float f) {
    unsigned u;
    asm("cvt.rna.tf32.f32 %0, %1;" : "=r"(u) : "f"(f));
    return u;
}
__device__ __forceinline__ void mma_tf32(float* d, const unsigned* a, const unsigned* b) {
    asm volatile(
        "mma.sync.aligned.m16n8k8.row.col.f32.tf32.tf32.f32 "
        "{%0,%1,%2,%3}, {%4,%5,%6,%7}, {%8,%9}, {%0,%1,%2,%3};"
        : "+f"(d[0]), "+f"(d[1]), "+f"(d[2]), "+f"(d[3])
        : "r"(a[0]), "r"(a[1]), "r"(a[2]), "r"(a[3]), "r"(b[0]), "r"(b[1]));
}
__device__ __forceinline__ float2 ldh2(const __half* p) {
    return __half22float2(*(const __half2*)p);
}

// ---------------- 1. pack weights + biases ----------------
__global__ void pack_kernel(const float* __restrict__ skip_film_W,
                            const float* __restrict__ skip_W,
                            const float* __restrict__ film_lin_W,
                            const float* __restrict__ film_film_W,
                            const float* __restrict__ film_film_b,
                            const float* __restrict__ skip_film_b,
                            const float* __restrict__ gat_W) {
    int stride = blockDim.x * gridDim.x;
    for (int idx = blockIdx.x * blockDim.x + threadIdx.x; idx < 64 * YW; idx += stride) {
        int d = idx / YW, j = idx % YW;
        float v;
        if (j < 128)        v = skip_film_W[d * 128 + j];
        else if (j < 192)   v = skip_W[d * 64 + (j - 128)];
        else if (j < 384) { int r = (j - 192) >> 6, h = (j - 192) & 63;
                            v = film_lin_W[r * 4096 + d * 64 + h]; }
        else if (j < 768) { int r = (j - 384) >> 7, c = (j - 384) & 127;
                            v = film_film_W[r * 8192 + d * 128 + c]; }
        else                v = gat_W[d * 64 + (j - 768)];
        d_Wcat[idx] = v;
    }
    for (int j = blockIdx.x * blockDim.x + threadIdx.x; j < YW; j += stride) {
        float b = 0.f;
        if (j < 128)                 b = skip_film_b[j];
        else if (j >= 384 && j < 768) { int r = (j - 384) >> 7, c = (j - 384) & 127;
                                        b = film_film_b[r * 128 + c]; }
        d_bcat[j] = b;
    }
}

// ---------------- 2. zero scratch ----------------
__global__ void zero_kernel() {
    int stride = blockDim.x * gridDim.x;
    int t = blockIdx.x * blockDim.x + threadIdx.x;
    for (int i = t; i < NN; i += stride) { d_hist[i] = 0; d_cursor[i] = 0; }
    for (int i = t; i < GG * 128; i += stride) { d_poolmax[i] = 0; d_poolsum[i] = 0.f; }
    for (int i = t; i < GG; i += stride)      d_gcnt[i] = 0;
}

// ---------------- 3. tensor-core GEMM (3xTF32 split) ----------------
__global__ __launch_bounds__(256) void gemm_tc_kernel(const float* __restrict__ A, int n) {
    __shared__ float As[128][68];
    __shared__ float Bs[64][72];
    int row0 = blockIdx.x * 128;
    int col0 = blockIdx.y * 64;
    int tid = threadIdx.x;

    #pragma unroll
    for (int i = 0; i < 8; i++) {
        int e = i * 256 + tid;
        int r = e >> 4;
        int c4 = (e & 15) << 2;
        float4 v = make_float4(0.f, 0.f, 0.f, 0.f);
        if (row0 + r < n) v = *(const float4*)(A + (size_t)(row0 + r) * 64 + c4);
        As[r][c4] = v.x; As[r][c4 + 1] = v.y; As[r][c4 + 2] = v.z; As[r][c4 + 3] = v.w;
    }
    #pragma unroll
    for (int i = 0; i < 4; i++) {
        int e = i * 256 + tid;
        int k = e >> 4;
        int c4 = (e & 15) << 2;
        float4 v = *(const float4*)(d_Wcat + k * YW + col0 + c4);
        Bs[k][c4] = v.x; Bs[k][c4 + 1] = v.y; Bs[k][c4 + 2] = v.z; Bs[k][c4 + 3] = v.w;
    }
    __syncthreads();

    int warp = tid >> 5, lane = tid & 31;
    int wm = (warp >> 1) * 32;
    int wn = (warp & 1) * 32;
    int lr = lane >> 2;
    int lc = lane & 3;

    float acc[2][4][4] = {};
    #pragma unroll
    for (int k0 = 0; k0 < 64; k0 += 8) {
        unsigned abig[2][4], asml[2][4];
        #pragma unroll
        for (int mi = 0; mi < 2; mi++) {
            int r = wm + mi * 16 + lr;
            float a0 = As[r][k0 + lc];
            float a1 = As[r + 8][k0 + lc];
            float a2 = As[r][k0 + 4 + lc];
            float a3 = As[r + 8][k0 + 4 + lc];
            abig[mi][0] = f2tf(a0); asml[mi][0] = f2tf(a0 - __uint_as_float(abig[mi][0]));
            abig[mi][1] = f2tf(a1); asml[mi][1] = f2tf(a1 - __uint_as_float(abig[mi][1]));
            abig[mi][2] = f2tf(a2); asml[mi][2] = f2tf(a2 - __uint_as_float(abig[mi][2]));
            abig[mi][3] = f2tf(a3); asml[mi][3] = f2tf(a3 - __uint_as_float(abig[mi][3]));
        }
        unsigned bbig[4][2], bsml[4][2];
        #pragma unroll
        for (int ni = 0; ni < 4; ni++) {
            int c = wn + ni * 8 + lr;
            float b0 = Bs[k0 + lc][c];
            float b1 = Bs[k0 + 4 + lc][c];
            bbig[ni][0] = f2tf(b0); bsml[ni][0] = f2tf(b0 - __uint_as_float(bbig[ni][0]));
            bbig[ni][1] = f2tf(b1); bsml[ni][1] = f2tf(b1 - __uint_as_float(bbig[ni][1]));
        }
        #pragma unroll
        for (int mi = 0; mi < 2; mi++)
            #pragma unroll
            for (int ni = 0; ni < 4; ni++) {
                mma_tf32(acc[mi][ni], abig[mi], bbig[ni]);
                mma_tf32(acc[mi][ni], abig[mi], bsml[ni]);
                mma_tf32(acc[mi][ni], asml[mi], bbig[ni]);
            }
    }

    bool is_half = (col0 >= 192);   // uniform per block
    #pragma unroll
    for (int mi = 0; mi < 2; mi++) {
        #pragma unroll
        for (int ni = 0; ni < 4; ni++) {
            int c = col0 + wn + ni * 8 + 2 * lc;
            float b0 = d_bcat[c], b1 = d_bcat[c + 1];
            int r0 = row0 + wm + mi * 16 + lr;
            #pragma unroll
            for (int rr = 0; rr < 2; rr++) {
                int r = r0 + rr * 8;
                if (r >= n) continue;
                float v0 = acc[mi][ni][rr * 2] + b0;
                float v1 = acc[mi][ni][rr * 2 + 1] + b1;
                if (is_half) {
                    *(__half2*)(d_Yh + (size_t)r * YH + (c - 192)) = __floats2half2_rn(v0, v1);
                } else {
                    *(float2*)(d_Y192 + (size_t)r * 192 + c) = make_float2(v0, v1);
                }
            }
        }
    }
}

// ---------------- 4. node epilogue: attention dot products --------------------
__global__ void node_epi_kernel(int n, const float* __restrict__ att_src,
                                const float* __restrict__ att_dst) {
    int w = (blockIdx.x * blockDim.x + threadIdx.x) >> 5;
    int l = threadIdx.x & 31;
    if (w >= n) return;
    const __half* xph = d_Yh + (size_t)w * YH + 576;
    float xp0 = __half2float(xph[l]), xp1 = __half2float(xph[l + 32]);
    float ps = xp0 * att_src[l] + xp1 * att_src[l + 32];
    float pd = xp0 * att_dst[l] + xp1 * att_dst[l + 32];
    #pragma unroll
    for (int off = 16; off > 0; off >>= 1) {
        ps += __shfl_down_sync(0xffffffffu, ps, off);
        pd += __shfl_down_sync(0xffffffffu, pd, off);
    }
    if (l == 0) { d_as[w] = ps; d_ad[w] = pd; }
}

// ---------------- 5. counting sort of edges by dst ----------------------------
__global__ void hist_kernel(int ne, const int* __restrict__ ei) {
    int e = blockIdx.x * blockDim.x + threadIdx.x;
    if (e >= ne) return;
    atomicAdd(&d_hist[ei[ne + e]], 1);
}

// 5a. per-block local exclusive scan + block sums
__global__ __launch_bounds__(SCAN_B) void scan_local_kernel() {
    __shared__ int warp_tot[32];
    int b = blockIdx.x, tid = threadIdx.x, lane = tid & 31, wid = tid >> 5;
    int i = b * SCAN_B + tid;
    int v = (i < NN) ? d_hist[i] : 0;
    int x = v;
    #pragma unroll
    for (int o = 1; o < 32; o <<= 1) {
        int y = __shfl_up_sync(0xffffffffu, x, o);
        if (lane >= o) x += y;
    }
    if (lane == 31) warp_tot[wid] = x;
    __syncthreads();
    if (wid == 0) {
        int w = warp_tot[lane];
        #pragma unroll
        for (int o = 1; o < 32; o <<= 1) {
            int y = __shfl_up_sync(0xffffffffu, w, o);
            if (lane >= o) w += y;
        }
        warp_tot[lane] = w;
    }
    __syncthreads();
    int incl = x + (wid > 0 ? warp_tot[wid - 1] : 0);
    if (i < NN) d_segoff[i] = incl - v;     // local exclusive
    if (tid == SCAN_B - 1) d_blksum[b] = incl;
}

// 5b. scan the SCAN_NB (=49) block sums with one warp
__global__ void scan_mid_kernel() {
    int l = threadIdx.x;   // 32 threads
    int a0 = (l < SCAN_NB) ? d_blksum[l] : 0;
    int a1 = (32 + l < SCAN_NB) ? d_blksum[32 + l] : 0;
    int x0 = a0;
    #pragma unroll
    for (int o = 1; o < 32; o <<= 1) {
        int y = __shfl_up_sync(0xffffffffu, x0, o);
        if (l >= o) x0 += y;
    }
    int tot0 = __shfl_sync(0xffffffffu, x0, 31);
    int x1 = a1;
    #pragma unroll
    for (int o = 1; o < 32; o <<= 1) {
        int y = __shfl_up_sync(0xffffffffu, x1, o);
        if (l >= o) x1 += y;
    }
    if (l < SCAN_NB)      d_blkoff[l] = x0 - a0;
    if (32 + l < SCAN_NB) d_blkoff[32 + l] = tot0 + x1 - a1;
    int tot1 = __shfl_sync(0xffffffffu, x1, 31);
    if (l == 0) d_segoff[NN] = tot0 + tot1;
}

// 5c. add block offsets
__global__ void scan_add_kernel() {
    int i = blockIdx.x * blockDim.x + threadIdx.x;
    if (i < NN) d_segoff[i] += d_blkoff[i >> 10];
}

__global__ void scatter_kernel(int ne, const int* __restrict__ ei,
                               const int* __restrict__ et) {
    int e = blockIdx.x * blockDim.x + threadIdx.x;
    if (e >= ne) return;
    int s = ei[e], d = ei[ne + e], t = et[e];
    int pos = d_segoff[d] + atomicAdd(&d_cursor[d], 1);
    d_sorted[pos] = s | (t << 16);
}

// ---------------- 6. fused aggregation + pooling: one warp per dst ------------
// Each lane owns h = {2l, 2l+1}. Atomic-free FiLM/GAT aggregation in registers;
// pooling atomics at the end. exp(e) computed once per edge on the owning lane
// during the load phase, then broadcast.
__global__ __launch_bounds__(256) void agg_kernel(int n, const int* __restrict__ gb,
                                                  const float* __restrict__ gat_b) {
    int d = (blockIdx.x * blockDim.x + threadIdx.x) >> 5;
    int l = threadIdx.x & 31;
    if (d >= n) return;

    const __half* yh_d = d_Yh + (size_t)d * YH;
    float2 be0 = ldh2(yh_d + 192 + 0 * 128 + 2 * l);
    float2 ga0 = ldh2(yh_d + 192 + 0 * 128 + 64 + 2 * l);
    float2 be1 = ldh2(yh_d + 192 + 1 * 128 + 2 * l);
    float2 ga1 = ldh2(yh_d + 192 + 1 * 128 + 64 + 2 * l);
    float2 be2 = ldh2(yh_d + 192 + 2 * 128 + 2 * l);
    float2 ga2 = ldh2(yh_d + 192 + 2 * 128 + 64 + 2 * l);

    float f0x = 0.f, f0y = 0.f, f1x = 0.f, f1y = 0.f, f2x = 0.f, f2y = 0.f;
    float gx = 0.f, gy = 0.f;
    float denom = 0.f;
    int c0 = 0, c1 = 0, c2 = 0;
    float ad_d = d_ad[d];

    int beg = d_segoff[d], end = d_segoff[d + 1];
    for (int base = beg; base < end; base += 32) {
        int i = base + l;
        int pk = 0; float ex = 0.f;
        if (i < end) {
            pk = d_sorted[i];
            ex = expf(lrelu(d_as[pk & 0xFFFF] + ad_d));
        }
        int m = min(32, end - base);
        for (int j = 0; j < m; j++) {
            int pkj  = __shfl_sync(0xffffffffu, pk, j);
            float exj = __shfl_sync(0xffffffffu, ex, j);
            int s = pkj & 0xFFFF, t = pkj >> 16;
            denom += exj;
            const __half* yh_s = d_Yh + (size_t)s * YH;
            float2 xp = ldh2(yh_s + 576 + 2 * l);
            gx += exj * xp.x; gy += exj * xp.y;
            if (t == 0) {
                float2 xr = ldh2(yh_s + 0 * 64 + 2 * l);
                f0x += frelu(ga0.x * xr.x + be0.x);
                f0y += frelu(ga0.y * xr.y + be0.y);
                c0++;
            } else if (t == 1) {
                float2 xr = ldh2(yh_s + 1 * 64 + 2 * l);
                f1x += frelu(ga1.x * xr.x + be1.x);
                f1y += frelu(ga1.y * xr.y + be1.y);
                c1++;
            } else {
                float2 xr = ldh2(yh_s + 2 * 64 + 2 * l);
                f2x += frelu(ga2.x * xr.x + be2.x);
                f2y += frelu(ga2.y * xr.y + be2.y);
                c2++;
            }
        }
    }

    // GAT self loop
    float ex_self = expf(lrelu(d_as[d] + ad_d));
    denom += ex_self;
    float2 xp_d = ldh2(yh_d + 576 + 2 * l);
    gx += ex_self * xp_d.x; gy += ex_self * xp_d.y;
    float rden = 1.f / denom;

    float r0 = 1.f / fmaxf((float)c0, 1.f);
    float r1 = 1.f / fmaxf((float)c1, 1.f);
    float r2 = 1.f / fmaxf((float)c2, 1.f);
    float filmx = f0x * r0 + f1x * r1 + f2x * r2;
    float filmy = f0y * r0 + f1y * r1 + f2y * r2;

    const float* yr = d_Y192 + (size_t)d * 192;
    float2 fsb = *(const float2*)(yr + 2 * l);         // fs beta
    float2 fsg = *(const float2*)(yr + 64 + 2 * l);    // fs gamma
    float2 skv = *(const float2*)(yr + 128 + 2 * l);   // x @ skip_W
    float v1x = frelu(frelu(fsg.x * skv.x + fsb.x) + filmx);
    float v1y = frelu(frelu(fsg.y * skv.y + fsb.y) + filmy);

    float v2x = frelu(gx * rden + gat_b[2 * l]);
    float v2y = frelu(gy * rden + gat_b[2 * l + 1]);

    int g = __shfl_sync(0xffffffffu, (l == 0) ? gb[d] : 0, 0);
    int pbase = g * 128 + 2 * l;
    atomicMax(&d_poolmax[pbase],     __float_as_int(v1x));
    atomicMax(&d_poolmax[pbase + 1], __float_as_int(v1y));
    atomicMax(&d_poolmax[pbase + 64],     __float_as_int(v2x));
    atomicMax(&d_poolmax[pbase + 65], __float_as_int(v2y));
    atomicAdd(&d_poolsum[pbase],     v1x);
    atomicAdd(&d_poolsum[pbase + 1], v1y);
    atomicAdd(&d_poolsum[pbase + 64],     v2x);
    atomicAdd(&d_poolsum[pbase + 65], v2y);
    if (l == 0) atomicAdd(&d_gcnt[g], 1);
}

// ---------------- 7. final MLP + log_softmax ----------------
__global__ void final_kernel(const float* __restrict__ lin_W, const float* __restrict__ lin_b,
                             const float* __restrict__ fc_W, const float* __restrict__ fc_b,
                             float* __restrict__ out) {
    int g = blockIdx.x, t = threadIdx.x;   // 64 threads
    __shared__ float pooled[256];
    __shared__ float hid[64];
    __shared__ float logits[CC];
    __shared__ float mx, lse;
    float cm = fmaxf((float)d_gcnt[g], 1.f);
    for (int j = t; j < 128; j += 64) {
        pooled[j] = __int_as_float(d_poolmax[g * 128 + j]);
        pooled[128 + j] = d_poolsum[g * 128 + j] / cm;
    }
    __syncthreads();
    float hs = lin_b[t];
    #pragma unroll 4
    for (int k = 0; k < 256; k++) hs = fmaf(pooled[k], lin_W[k * 64 + t], hs);
    hid[t] = frelu(hs);
    __syncthreads();
    if (t < CC) {
        float s = fc_b[t];
        #pragma unroll
        for (int h = 0; h < 64; h++) s = fmaf(hid[h], fc_W[h * CC + t], s);
        logits[t] = s;
    }
    __syncthreads();
    if (t == 0) {
        float m = logits[0];
        #pragma unroll
        for (int c = 1; c < CC; c++) m = fmaxf(m, logits[c]);
        float sum = 0.f;
        #pragma unroll
        for (int c = 0; c < CC; c++) sum += expf(logits[c] - m);
        mx = m; lse = logf(sum);
    }
    __syncthreads();
    if (t < CC) out[g * CC + t] = logits[t] - mx - lse;
}

// ---------------- launch ----------------
extern "C" void kernel_launch(void* const* d_in, const int* in_sizes, int n_in,
                              void* d_out, int out_size) {
    const float* x           = (const float*)d_in[0];
    const int*   edge_index  = (const int*)d_in[1];
    const int*   edge_type   = (const int*)d_in[2];
    const int*   graph_batch = (const int*)d_in[3];
    const float* film_lin_W  = (const float*)d_in[4];
    const float* film_film_W = (const float*)d_in[5];
    const float* film_film_b = (const float*)d_in[6];
    const float* skip_W      = (const float*)d_in[7];
    const float* skip_film_W = (const float*)d_in[8];
    const float* skip_film_b = (const float*)d_in[9];
    const float* gat_W       = (const float*)d_in[10];
    const float* gat_att_src = (const float*)d_in[11];
    const float* gat_att_dst = (const float*)d_in[12];
    const float* gat_b       = (const float*)d_in[13];
    const float* lin_W       = (const float*)d_in[14];
    const float* lin_b       = (const float*)d_in[15];
    const float* fc_W        = (const float*)d_in[16];
    const float* fc_b        = (const float*)d_in[17];
    float* out = (float*)d_out;

    int n = in_sizes[0] / FIN;     // 50000
    int ne = in_sizes[2];          // 800000

    pack_kernel<<<64, 256>>>(skip_film_W, skip_W, film_lin_W, film_film_W,
                             film_film_b, skip_film_b, gat_W);
    zero_kernel<<<256, 256>>>();

    // fork: sort chain on g_s2, GEMM chain on the main (capture) stream
    cudaEventRecord(g_evFork, 0);
    cudaStreamWaitEvent(g_s2, g_evFork, 0);

    hist_kernel<<<(ne + 255) / 256, 256, 0, g_s2>>>(ne, edge_index);
    scan_local_kernel<<<SCAN_NB, SCAN_B, 0, g_s2>>>();
    scan_mid_kernel<<<1, 32, 0, g_s2>>>();
    scan_add_kernel<<<(NN + 255) / 256, 256, 0, g_s2>>>();
    scatter_kernel<<<(ne + 255) / 256, 256, 0, g_s2>>>(ne, edge_index, edge_type);
    cudaEventRecord(g_evJoin, g_s2);

    dim3 ggrid((n + 127) / 128, YW / 64);
    gemm_tc_kernel<<<ggrid, 256>>>(x, n);
    node_epi_kernel<<<(n + 7) / 8, 256>>>(n, gat_att_src, gat_att_dst);

    // join: agg needs both the sorted edges and Y
    cudaStreamWaitEvent(0, g_evJoin, 0);
    agg_kernel<<<(n + 7) / 8, 256>>>(n, graph_batch, gat_b);
    final_kernel<<<GG, 64>>>(lin_W, lin_b, fc_W, fc_b, out);
}